// round 13
// baseline (speedup 1.0000x reference)
#include <cuda_runtime.h>
#include <cstdint>

// Problem constants
#define BSZ   2048
#define DIM   1024
#define DWM   512
#define WIN   256
#define NH    8
#define HD    64
#define QKV_LD 1536
#define ATT_SCALE 0.125f

// Scratch (device globals: allocation-free rule)
__device__ float g_qkv[(size_t)BSZ * QKV_LD];   // 12 MB
__device__ float g_att[(size_t)BSZ * DWM];      // 4 MB
__device__ int   g_rows[BSZ];                   // compacted non-reset row ids
__device__ int   g_nrows;                       // count of non-reset rows

// ---------------- bool dtype helpers ------------------------------------------
__device__ __forceinline__ int bool_mode(const unsigned char* valid)
{
    unsigned char b0 = valid[0], b1 = valid[1];
    return (b0 == 0) ? 2 : (b1 != 0 ? 0 : 1);   // 0=u8, 1=i32, 2=f32
}
__device__ __forceinline__ bool read_bool(const void* p, long idx, int mode)
{
    if (mode == 1) return ((const int*)p)[idx] != 0;
    if (mode == 2) return ((const float*)p)[idx] != 0.0f;
    return ((const unsigned char*)p)[idx] != 0;
}

// ---------------- compaction: non-reset row list (1 CTA, 1024 threads) --------
__global__ void compact_kernel(const void* __restrict__ resetIn,
                               const void* __restrict__ validIn)
{
    __shared__ int cnt_s[1024];
    const int tid = threadIdx.x;
    const int mode = bool_mode((const unsigned char*)validIn);

    const bool a = !read_bool(resetIn, 2 * tid, mode);
    const bool c = !read_bool(resetIn, 2 * tid + 1, mode);
    const int cnt = (int)a + (int)c;
    cnt_s[tid] = cnt;
    __syncthreads();
    for (int off = 1; off < 1024; off <<= 1) {
        int add = (tid >= off) ? cnt_s[tid - off] : 0;
        int v   = cnt_s[tid];
        __syncthreads();
        cnt_s[tid] = v + add;
        __syncthreads();
    }
    int pos = cnt_s[tid] - cnt;
    if (a) g_rows[pos++] = 2 * tid;
    if (c) g_rows[pos]   = 2 * tid + 1;
    if (tid == 1023) g_nrows = cnt_s[1023];
}

// ---------------- tf32 helpers ------------------------------------------------
__device__ __forceinline__ uint32_t f2tf32(float f) {
    uint32_t u;
    asm("cvt.rna.tf32.f32 %0, %1;" : "=r"(u) : "f"(f));
    return u;
}
__device__ __forceinline__ void mma_tf32(float* d, const uint32_t* a, const uint32_t* b) {
    asm volatile(
        "mma.sync.aligned.m16n8k8.row.col.f32.tf32.tf32.f32 "
        "{%0,%1,%2,%3},{%4,%5,%6,%7},{%8,%9},{%0,%1,%2,%3};\n"
        : "+f"(d[0]), "+f"(d[1]), "+f"(d[2]), "+f"(d[3])
        : "r"(a[0]), "r"(a[1]), "r"(a[2]), "r"(a[3]), "r"(b[0]), "r"(b[1]));
}

// ===================== tf32 mma.sync GEMM, fragment-packed smem ===============
// C[m,n] = sum_k A[m,k]*B[n,k] + bias[n]
// CTA tile 128x128, K-tile 32, 256 threads = 8 warps (2m x 4n), warp tile 64x32.
// SMEM holds tiles in mma-fragment order:
//  A: per (16-row tile T, ks) block of 132 floats: lane*4 + j (j = a0..a3)
//     -> fragment load = one LDS.128 per (mt, ks)
//  B: per (8-col tile NT, ks) block of 66 floats: lane*2 + j (j = b0..b1)
//     -> fragment load = one LDS.64 per (nt, ks)
// Fragment map (PTX m16n8k8 tf32): A elem(row,kk): lane=(row&7)*4+(kk&3),
//   j=(row>=8)+2*(kk>=4).  B elem(n,kk): lane=(n&7)*4+(kk&3), j=(kk>=4).
#define BM 128
#define BN 128
#define BK 32
#define A_PACK (8 * 4 * 132)             // 4224 floats
#define B_PACK (16 * 4 * 66)             // 4224 floats
#define BUF_FLOATS (A_PACK + B_PACK)     // 8448
#define TCSM_BYTES (2 * BUF_FLOATS * 4)  // 67584 (opt-in)

// store one row-quad (4 consecutive k, tf32-converted) into packed A
__device__ __forceinline__ void stA(float* Abuf, int r, int q, uint4 t)
{
    int T = r >> 4, g = r & 7, half = (r >> 3) & 1;
    int ks = q >> 1, j = half + ((q & 1) << 1);
    float* p = Abuf + (T * 4 + ks) * 132 + (g << 4) + j;
    p[0]  = __uint_as_float(t.x);
    p[4]  = __uint_as_float(t.y);
    p[8]  = __uint_as_float(t.z);
    p[12] = __uint_as_float(t.w);
}
__device__ __forceinline__ void stB(float* Bbuf, int r, int q, uint4 t)
{
    int NT = r >> 3, ks = q >> 1, j = q & 1;
    float* p = Bbuf + (NT * 4 + ks) * 66 + ((r & 7) << 3) + j;
    p[0] = __uint_as_float(t.x);
    p[2] = __uint_as_float(t.y);
    p[4] = __uint_as_float(t.z);
    p[6] = __uint_as_float(t.w);
}

template<bool GATHER>
__device__ __forceinline__ void tc_gemm_body(
    const float* __restrict__ A, const float* __restrict__ Bw,
    const float* __restrict__ bias, float* __restrict__ C,
    int K, int ldc, int rowBase, int colB, int colC, int niter, int nrows)
{
    extern __shared__ float smem[];
    __shared__ int ridx_s[BM];

    const int tid  = threadIdx.x;
    const int lane = tid & 31;
    const int warp = tid >> 5;
    const int g    = lane >> 2;          // 0..7
    const int tg   = lane & 3;           // 0..3
    const int wm   = (warp >> 2) * 64;   // 0,64
    const int wn   = (warp & 3) * 32;    // 0,32,64,96
    const int T0   = wm >> 4;            // 0 or 4
    const int NT0  = wn >> 3;            // 0,4,8,12

    if (GATHER) {
        if (tid < BM) {
            int rr = rowBase + tid;
            ridx_s[tid] = (rr < nrows) ? g_rows[rr] : 0;
        }
        __syncthreads();
    }

    const float* Bbase = Bw + (size_t)colB * K;

    float acc[4][4][4];
    #pragma unroll
    for (int mt = 0; mt < 4; ++mt)
        #pragma unroll
        for (int nt = 0; nt < 4; ++nt)
            #pragma unroll
            for (int r = 0; r < 4; ++r) acc[mt][nt][r] = 0.f;

    float4 pa[4], pb[4];

    auto arow = [&](int row) -> const float* {
        int rr = GATHER ? ridx_s[row] : (rowBase + row);
        return A + (size_t)rr * K;
    };

    // ---- prefetch + store tile 0 ----
    #pragma unroll
    for (int i = 0; i < 4; ++i) {
        int idx = tid + (i << 8), row = idx >> 3, q = idx & 7;
        pa[i] = *(const float4*)(arow(row) + (q << 2));
        pb[i] = *(const float4*)(Bbase + (size_t)row * K + (q << 2));
    }
    {
        float* Abuf = smem;
        float* Bbuf = smem + A_PACK;
        #pragma unroll
        for (int i = 0; i < 4; ++i) {
            int idx = tid + (i << 8), row = idx >> 3, q = idx & 7;
            uint4 ta, tb;
            ta.x = f2tf32(pa[i].x); ta.y = f2tf32(pa[i].y);
            ta.z = f2tf32(pa[i].z); ta.w = f2tf32(pa[i].w);
            tb.x = f2tf32(pb[i].x); tb.y = f2tf32(pb[i].y);
            tb.z = f2tf32(pb[i].z); tb.w = f2tf32(pb[i].w);
            stA(Abuf, row, q, ta);
            stB(Bbuf, row, q, tb);
        }
    }
    __syncthreads();

    for (int it = 0; it < niter; ++it) {
        const int buf = it & 1;
        if (it + 1 < niter) {
            const int ko = (it + 1) * BK;
            #pragma unroll
            for (int i = 0; i < 4; ++i) {
                int idx = tid + (i << 8), row = idx >> 3, q = idx & 7;
                pa[i] = *(const float4*)(arow(row) + ko + (q << 2));
                pb[i] = *(const float4*)(Bbase + (size_t)row * K + ko + (q << 2));
            }
        }
        {
            const float* Abuf = smem + buf * BUF_FLOATS;
            const float* Bbuf = Abuf + A_PACK;
            #pragma unroll
            for (int ks = 0; ks < 4; ++ks) {
                float4 af[4];
                float2 bf[4];
                #pragma unroll
                for (int mt = 0; mt < 4; ++mt)
                    af[mt] = *(const float4*)(Abuf + ((T0 + mt) * 4 + ks) * 132 + (lane << 2));
                #pragma unroll
                for (int nt = 0; nt < 4; ++nt)
                    bf[nt] = *(const float2*)(Bbuf + ((NT0 + nt) * 4 + ks) * 66 + (lane << 1));
                #pragma unroll
                for (int mt = 0; mt < 4; ++mt)
                    #pragma unroll
                    for (int nt = 0; nt < 4; ++nt)
                        mma_tf32(acc[mt][nt],
                                 (const uint32_t*)&af[mt],
                                 (const uint32_t*)&bf[nt]);
            }
        }
        if (it + 1 < niter) {
            float* Abuf = smem + (buf ^ 1) * BUF_FLOATS;
            float* Bbuf = Abuf + A_PACK;
            #pragma unroll
            for (int i = 0; i < 4; ++i) {
                int idx = tid + (i << 8), row = idx >> 3, q = idx & 7;
                uint4 ta, tb;
                ta.x = f2tf32(pa[i].x); ta.y = f2tf32(pa[i].y);
                ta.z = f2tf32(pa[i].z); ta.w = f2tf32(pa[i].w);
                tb.x = f2tf32(pb[i].x); tb.y = f2tf32(pb[i].y);
                tb.z = f2tf32(pb[i].z); tb.w = f2tf32(pb[i].w);
                stA(Abuf, row, q, ta);
                stB(Bbuf, row, q, tb);
            }
            __syncthreads();
        }
    }

    // ---- epilogue: C = acc + bias ----
    #pragma unroll
    for (int mt = 0; mt < 4; ++mt) {
        #pragma unroll
        for (int nt = 0; nt < 4; ++nt) {
            int lr0 = wm + mt * 16 + g;
            int lr1 = lr0 + 8;
            int col = wn + nt * 8 + tg * 2;
            float b0 = bias[colB + col], b1 = bias[colB + col + 1];
            float2 v0 = make_float2(acc[mt][nt][0] + b0, acc[mt][nt][1] + b1);
            float2 v1 = make_float2(acc[mt][nt][2] + b0, acc[mt][nt][3] + b1);
            if (GATHER) {
                if (rowBase + lr0 < nrows)
                    *(float2*)(C + (size_t)ridx_s[lr0] * ldc + colC + col) = v0;
                if (rowBase + lr1 < nrows)
                    *(float2*)(C + (size_t)ridx_s[lr1] * ldc + colC + col) = v1;
            } else {
                *(float2*)(C + (size_t)(rowBase + lr0) * ldc + colC + col) = v0;
                *(float2*)(C + (size_t)(rowBase + lr1) * ldc + colC + col) = v1;
            }
        }
    }
}

// QKV kernel: y 0..3 -> V dense (all rows); y 4..11 -> Q/K gathered (non-reset)
__global__ __launch_bounds__(256) void qkv_gemm_tc(
    const float* __restrict__ x,
    const float* __restrict__ Wq, const float* __restrict__ bq,
    const float* __restrict__ Wk, const float* __restrict__ bk,
    const float* __restrict__ Wv, const float* __restrict__ bv)
{
    const int y = blockIdx.y;
    if (y < 4) {
        const int nc = y * BN;
        tc_gemm_body<false>(x, Wv, bv, g_qkv, DIM, QKV_LD,
                            blockIdx.x * BM, nc, 2 * DWM + nc, DIM / BK, BSZ);
    } else {
        const int q  = y - 4;          // 0..7
        const int zz = q >> 2;         // 0=Q, 1=K
        const int nc = (q & 3) * BN;
        const int nrows = g_nrows;
        if (blockIdx.x * BM >= nrows) return;
        const float* Bw = zz ? Wk : Wq;
        const float* bi = zz ? bk : bq;
        tc_gemm_body<true>(x, Bw, bi, g_qkv, DIM, QKV_LD,
                           blockIdx.x * BM, nc, zz * DWM + nc, DIM / BK, nrows);
    }
}

__global__ __launch_bounds__(256) void out_gemm_tc(
    const float* __restrict__ Wo, const float* __restrict__ bo,
    float* __restrict__ y)
{
    tc_gemm_body<false>(g_att, Wo, bo, y, DWM, DIM,
                        blockIdx.x * BM, blockIdx.y * BN, blockIdx.y * BN,
                        DWM / BK, BSZ);
}

// ---------------- Attention kernel: one CTA per batch row --------------------
// Reset rows: only freshly-written slot valid -> out = v_new exactly (early exit).
__global__ __launch_bounds__(256) void attn_kernel(
    const float* __restrict__ wmK, const float* __restrict__ wmV,
    const void* __restrict__ validIn,
    const void* __restrict__ resetIn,
    const int* __restrict__ ptrIn)
{
    __shared__ float q_s[DWM];
    __shared__ float att_s[NH][WIN];
    __shared__ unsigned char valid_s[WIN];

    const int b    = blockIdx.x;
    const int tid  = threadIdx.x;   // 256
    const int lane = tid & 31;
    const int warp = tid >> 5;      // 8 warps == 8 heads

    const int mode = bool_mode((const unsigned char*)validIn);
    const bool rs = read_bool(resetIn, b, mode);

    const float* qrow  = g_qkv + (size_t)b * QKV_LD;
    const float* knew  = qrow + DWM;
    const float* vnew  = qrow + 2 * DWM;

    if (rs) {
        float2 v0 = *(const float2*)(vnew + tid * 2);
        *(float2*)(g_att + (size_t)b * DWM + tid * 2) = v0;
        return;
    }

    const int p = ptrIn[b];
    const float* Kbase = wmK + (size_t)b * WIN * DWM;
    const float* Vbase = wmV + (size_t)b * WIN * DWM;

    for (int i = tid; i < DWM; i += 256) q_s[i] = qrow[i];
    if (tid < WIN)
        valid_s[tid] = read_bool(validIn, (size_t)b * WIN + tid, mode) ? 1 : 0;
    __syncthreads();

    const float NEG_INF = __int_as_float(0xff800000);

    // ---- phase 1: logits (uniform over stored K; slot p patched after) ----
    {
        const int h = warp;
        float2 qv = *(const float2*)(q_s + h * HD + lane * 2);
        const float2* kp = (const float2*)(Kbase + h * HD + lane * 2);
        for (int w0 = 0; w0 < WIN; w0 += 8) {
            float s[8];
            #pragma unroll
            for (int u = 0; u < 8; ++u) {
                float2 kv = __ldcs(kp + (size_t)(w0 + u) * (DWM / 2));
                s[u] = kv.x * qv.x + kv.y * qv.y;
            }
            #pragma unroll
            for (int u = 0; u < 8; ++u) {
                #pragma unroll
                for (int o = 16; o > 0; o >>= 1)
                    s[u] += __shfl_xor_sync(0xffffffffu, s[u], o);
            }
            if (lane == 0) {
                #pragma unroll
                for (int u = 0; u < 8; ++u) {
                    int w = w0 + u;
                    bool val = (valid_s[w] != 0);
                    att_s[h][w] = val ? s[u] * ATT_SCALE : NEG_INF;
                }
            }
        }
        {
            float2 kv = *(const float2*)(knew + h * HD + lane * 2);
            float s = kv.x * qv.x + kv.y * qv.y;
            #pragma unroll
            for (int o = 16; o > 0; o >>= 1)
                s += __shfl_xor_sync(0xffffffffu, s, o);
            if (lane == 0) att_s[h][p] = s * ATT_SCALE;
        }
    }
    __syncthreads();

    // ---- phase 2: per-head softmax (warp h) ----
    {
        const int h = warp;
        float e[8];
        float m = NEG_INF;
        #pragma unroll
        for (int j = 0; j < 8; ++j) {
            e[j] = att_s[h][lane + 32 * j];
            m = fmaxf(m, e[j]);
        }
        #pragma unroll
        for (int o = 16; o > 0; o >>= 1)
            m = fmaxf(m, __shfl_xor_sync(0xffffffffu, m, o));
        float sum = 0.f;
        #pragma unroll
        for (int j = 0; j < 8; ++j) {
            e[j] = __expf(e[j] - m);
            sum += e[j];
        }
        #pragma unroll
        for (int o = 16; o > 0; o >>= 1)
            sum += __shfl_xor_sync(0xffffffffu, sum, o);
        float inv = (sum > 0.f) ? (1.0f / sum) : 0.f;
        #pragma unroll
        for (int j = 0; j < 8; ++j)
            att_s[h][lane + 32 * j] = e[j] * inv;
    }
    __syncthreads();

    // ---- phase 3: AV, uniform over stored V; correction for slot p ----
    {
        const int d = tid * 2;
        const int h = tid >> 5;
        float ax = 0.f, ay = 0.f;
        const float2* vp = (const float2*)(Vbase + d);
        for (int w0 = 0; w0 < WIN; w0 += 8) {
            float2 vv[8];
            #pragma unroll
            for (int u = 0; u < 8; ++u)
                vv[u] = __ldcs(vp + (size_t)(w0 + u) * (DWM / 2));
            #pragma unroll
            for (int u = 0; u < 8; ++u) {
                float pw = att_s[h][w0 + u];
                ax = fmaf(pw, vv[u].x, ax);
                ay = fmaf(pw, vv[u].y, ay);
            }
        }
        {
            float2 vold = *(const float2*)(Vbase + (size_t)p * DWM + d);
            float2 vn   = *(const float2*)(vnew + d);
            float pw = att_s[h][p];
            ax = fmaf(pw, vn.x - vold.x, ax);
            ay = fmaf(pw, vn.y - vold.y, ay);
        }
        *(float2*)(g_att + (size_t)b * DWM + d) = make_float2(ax, ay);
    }
}

// ---------------- launcher ---------------------------------------------------
extern "C" void kernel_launch(void* const* d_in, const int* in_sizes, int n_in,
                              void* d_out, int out_size)
{
    const float* x     = (const float*)d_in[0];
    const void*  reset = d_in[1];
    const float* wmK   = (const float*)d_in[2];
    const float* wmV   = (const float*)d_in[3];
    const void*  valid = d_in[4];
    const int*   ptr   = (const int*)d_in[5];
    const float* Wq    = (const float*)d_in[6];
    const float* bq    = (const float*)d_in[7];
    const float* Wk    = (const float*)d_in[8];
    const float* bk    = (const float*)d_in[9];
    const float* Wv    = (const float*)d_in[10];
    const float* bv    = (const float*)d_in[11];
    const float* Wo    = (const float*)d_in[12];
    const float* bo    = (const float*)d_in[13];
    float*       y     = (float*)d_out;

    cudaFuncSetAttribute(qkv_gemm_tc, cudaFuncAttributeMaxDynamicSharedMemorySize, TCSM_BYTES);
    cudaFuncSetAttribute(out_gemm_tc, cudaFuncAttributeMaxDynamicSharedMemorySize, TCSM_BYTES);

    compact_kernel<<<1, 1024>>>(reset, valid);

    dim3 gQKV(BSZ / BM, 12);            // 16 x 12; Q/K tail tiles self-disable
    qkv_gemm_tc<<<gQKV, 256, TCSM_BYTES>>>(x, Wq, bq, Wk, bk, Wv, bv);

    attn_kernel<<<BSZ, 256>>>(wmK, wmV, valid, reset, ptr);

    dim3 gOut(BSZ / BM, DIM / BN);      // 16 x 8 = 128 CTAs
    out_gemm_tc<<<gOut, 256, TCSM_BYTES>>>(Wo, bo, y);
}

// round 14
// speedup vs baseline: 1.1616x; 1.1616x over previous
#include <cuda_runtime.h>
#include <cstdint>

// Problem constants
#define BSZ   2048
#define DIM   1024
#define DWM   512
#define WIN   256
#define NH    8
#define HD    64
#define QKV_LD 1536
#define ATT_SCALE 0.125f

// Scratch (device globals: allocation-free rule)
__device__ float g_qkv[(size_t)BSZ * QKV_LD];   // 12 MB
__device__ float g_att[(size_t)BSZ * DWM];      // 4 MB (tf32-valued)
__device__ int   g_rows[BSZ];                   // compacted non-reset row ids
__device__ int   g_nrows;                       // count of non-reset rows
// tf32-pre-rounded operands
__device__ float g_xt [(size_t)BSZ * DIM];      // 8 MB
__device__ float g_wqt[(size_t)DWM * DIM];      // 2 MB
__device__ float g_wkt[(size_t)DWM * DIM];
__device__ float g_wvt[(size_t)DWM * DIM];
__device__ float g_wot[(size_t)DIM * DWM];

// ---------------- bool dtype helpers ------------------------------------------
__device__ __forceinline__ int bool_mode(const unsigned char* valid)
{
    unsigned char b0 = valid[0], b1 = valid[1];
    return (b0 == 0) ? 2 : (b1 != 0 ? 0 : 1);   // 0=u8, 1=i32, 2=f32
}
__device__ __forceinline__ bool read_bool(const void* p, long idx, int mode)
{
    if (mode == 1) return ((const int*)p)[idx] != 0;
    if (mode == 2) return ((const float*)p)[idx] != 0.0f;
    return ((const unsigned char*)p)[idx] != 0;
}

// ---------------- tf32 helpers ------------------------------------------------
__device__ __forceinline__ uint32_t f2tf32(float f) {
    uint32_t u;
    asm("cvt.rna.tf32.f32 %0, %1;" : "=r"(u) : "f"(f));
    return u;
}
__device__ __forceinline__ void mma_tf32(float* d, const uint32_t* a, const uint32_t* b) {
    asm volatile(
        "mma.sync.aligned.m16n8k8.row.col.f32.tf32.tf32.f32 "
        "{%0,%1,%2,%3},{%4,%5,%6,%7},{%8,%9},{%0,%1,%2,%3};\n"
        : "+f"(d[0]), "+f"(d[1]), "+f"(d[2]), "+f"(d[3])
        : "r"(a[0]), "r"(a[1]), "r"(a[2]), "r"(a[3]), "r"(b[0]), "r"(b[1]));
}
__device__ __forceinline__ void cp16(uint32_t dst_smem, const void* src) {
    asm volatile("cp.async.cg.shared.global [%0], [%1], 16;"
                 :: "r"(dst_smem), "l"(src));
}

// ---------------- compaction: non-reset row list (1 CTA, 1024 threads) --------
__global__ void compact_kernel(const void* __restrict__ resetIn,
                               const void* __restrict__ validIn)
{
    __shared__ int cnt_s[1024];
    const int tid = threadIdx.x;
    const int mode = bool_mode((const unsigned char*)validIn);

    const bool a = !read_bool(resetIn, 2 * tid, mode);
    const bool c = !read_bool(resetIn, 2 * tid + 1, mode);
    const int cnt = (int)a + (int)c;
    cnt_s[tid] = cnt;
    __syncthreads();
    for (int off = 1; off < 1024; off <<= 1) {
        int add = (tid >= off) ? cnt_s[tid - off] : 0;
        int v   = cnt_s[tid];
        __syncthreads();
        cnt_s[tid] = v + add;
        __syncthreads();
    }
    int pos = cnt_s[tid] - cnt;
    if (a) g_rows[pos++] = 2 * tid;
    if (c) g_rows[pos]   = 2 * tid + 1;
    if (tid == 1023) g_nrows = cnt_s[1023];
}

// ---------------- pre-convert x + weights to tf32 values ----------------------
#define X_F4  (BSZ * DIM / 4)     // 524288
#define W_F4  (DWM * DIM / 4)     // 131072
#define TOT_F4 (X_F4 + 4 * W_F4)  // 1048576
__global__ __launch_bounds__(256) void convert_kernel(
    const float* __restrict__ x,  const float* __restrict__ wq,
    const float* __restrict__ wk, const float* __restrict__ wv,
    const float* __restrict__ wo)
{
    const int gid = blockIdx.x * 256 + threadIdx.x;   // grid 2048 -> 524288 thr
    #pragma unroll
    for (int rep = 0; rep < 2; ++rep) {
        int i = gid + rep * 524288;
        const float4* s; uint4* d; int off;
        if (i < X_F4)                 { s = (const float4*)x;  d = (uint4*)g_xt;  off = i; }
        else if (i < X_F4 + W_F4)     { s = (const float4*)wq; d = (uint4*)g_wqt; off = i - X_F4; }
        else if (i < X_F4 + 2*W_F4)   { s = (const float4*)wk; d = (uint4*)g_wkt; off = i - X_F4 - W_F4; }
        else if (i < X_F4 + 3*W_F4)   { s = (const float4*)wv; d = (uint4*)g_wvt; off = i - X_F4 - 2*W_F4; }
        else                          { s = (const float4*)wo; d = (uint4*)g_wot; off = i - X_F4 - 3*W_F4; }
        float4 v = s[off];
        uint4 t;
        t.x = f2tf32(v.x); t.y = f2tf32(v.y); t.z = f2tf32(v.z); t.w = f2tf32(v.w);
        d[off] = t;
    }
}

// ===================== tf32 mma.sync GEMM, 4-stage cp.async ===================
// C[m,n] = sum_k A[m,k]*B[n,k] + bias[n]; A,B pre-rounded to tf32 values.
// CTA tile 128x128, K-tile 32, 256 threads = 8 warps (2m x 4n), warp tile 64x32.
// SMEM: R11-proven XOR-swizzled layout, 4 pipeline stages.
#define BM 128
#define BN 128
#define BK 32
#define NSTAGE 4
#define A_FL (BM * BK)                    // 4096 floats
#define B_FL (BN * BK)                    // 4096
#define STAGE_FLOATS (A_FL + B_FL)        // 8192
#define STAGE_BYTES  (STAGE_FLOATS * 4)   // 32768
#define TCSM_BYTES   (NSTAGE * STAGE_BYTES)  // 131072 (opt-in)

template<bool GATHER>
__device__ __forceinline__ void tc_gemm_body(
    const float* __restrict__ A, const float* __restrict__ Bw,
    const float* __restrict__ bias, float* __restrict__ C,
    int K, int ldc, int rowBase, int colB, int colC, int niter, int nrows)
{
    extern __shared__ float smem[];
    __shared__ int ridx_s[BM];

    const int tid  = threadIdx.x;
    const int lane = tid & 31;
    const int warp = tid >> 5;
    const int g    = lane >> 2;          // 0..7
    const int tg   = lane & 3;           // 0..3
    const int wm   = (warp >> 2) * 64;   // 0,64
    const int wn   = (warp & 3) * 32;    // 0,32,64,96

    if (GATHER) {
        if (tid < BM) {
            int rr = rowBase + tid;
            ridx_s[tid] = (rr < nrows) ? g_rows[rr] : 0;
        }
        __syncthreads();
    }

    const float* Bbase = Bw + (size_t)colB * K;
    const uint32_t smem_u = (uint32_t)__cvta_generic_to_shared(smem);

    float acc[4][4][4];
    #pragma unroll
    for (int mt = 0; mt < 4; ++mt)
        #pragma unroll
        for (int nt = 0; nt < 4; ++nt)
            #pragma unroll
            for (int r = 0; r < 4; ++r) acc[mt][nt][r] = 0.f;

    auto arow = [&](int row) -> const float* {
        int rr = GATHER ? ridx_s[row] : (rowBase + row);
        return A + (size_t)rr * K;
    };
    auto issue_tile = [&](int stage, int ko) {
        uint32_t abase = smem_u + stage * STAGE_BYTES;
        uint32_t bbase = abase + A_FL * 4;
        #pragma unroll
        for (int i = 0; i < 4; ++i) {
            int idx = tid + (i << 8), row = idx >> 3, q = idx & 7;
            uint32_t soff = (uint32_t)(row * BK + ((q ^ (row & 7)) << 2)) * 4u;
            cp16(abase + soff, arow(row) + ko + (q << 2));
            cp16(bbase + soff, Bbase + (size_t)row * K + ko + (q << 2));
        }
        asm volatile("cp.async.commit_group;");
    };

    // prologue: stages 0..NSTAGE-2
    const int npro = (niter < NSTAGE - 1) ? niter : (NSTAGE - 1);
    for (int s = 0; s < npro; ++s) issue_tile(s, s * BK);

    for (int it = 0; it < niter; ++it) {
        int allow = niter - it - 1;
        if (allow > NSTAGE - 2) allow = NSTAGE - 2;
        if (allow == 2)      asm volatile("cp.async.wait_group 2;");
        else if (allow == 1) asm volatile("cp.async.wait_group 1;");
        else                 asm volatile("cp.async.wait_group 0;");
        __syncthreads();

        if (it + NSTAGE - 1 < niter)
            issue_tile((it + NSTAGE - 1) & (NSTAGE - 1), (it + NSTAGE - 1) * BK);

        const uint32_t* Abuf = (const uint32_t*)(smem + (it & (NSTAGE - 1)) * STAGE_FLOATS);
        const uint32_t* Bbuf = Abuf + A_FL;
        #pragma unroll
        for (int ks = 0; ks < 4; ++ks) {
            uint32_t af[4][4], bf[4][2];
            const int g0 = ((2 * ks) ^ g) << 2;
            const int g1 = ((2 * ks + 1) ^ g) << 2;
            #pragma unroll
            for (int mt = 0; mt < 4; ++mt) {
                int r0 = wm + mt * 16 + g;
                int r1 = r0 + 8;
                af[mt][0] = Abuf[r0 * BK + g0 + tg];
                af[mt][1] = Abuf[r1 * BK + g0 + tg];
                af[mt][2] = Abuf[r0 * BK + g1 + tg];
                af[mt][3] = Abuf[r1 * BK + g1 + tg];
            }
            #pragma unroll
            for (int nt = 0; nt < 4; ++nt) {
                int n = wn + nt * 8 + g;
                bf[nt][0] = Bbuf[n * BK + g0 + tg];
                bf[nt][1] = Bbuf[n * BK + g1 + tg];
            }
            #pragma unroll
            for (int mt = 0; mt < 4; ++mt)
                #pragma unroll
                for (int nt = 0; nt < 4; ++nt)
                    mma_tf32(acc[mt][nt], af[mt], bf[nt]);
        }
    }

    // ---- epilogue: C = acc + bias ----
    #pragma unroll
    for (int mt = 0; mt < 4; ++mt) {
        #pragma unroll
        for (int nt = 0; nt < 4; ++nt) {
            int lr0 = wm + mt * 16 + g;
            int lr1 = lr0 + 8;
            int col = wn + nt * 8 + tg * 2;
            float b0 = bias[colB + col], b1 = bias[colB + col + 1];
            float2 v0 = make_float2(acc[mt][nt][0] + b0, acc[mt][nt][1] + b1);
            float2 v1 = make_float2(acc[mt][nt][2] + b0, acc[mt][nt][3] + b1);
            if (GATHER) {
                if (rowBase + lr0 < nrows)
                    *(float2*)(C + (size_t)ridx_s[lr0] * ldc + colC + col) = v0;
                if (rowBase + lr1 < nrows)
                    *(float2*)(C + (size_t)ridx_s[lr1] * ldc + colC + col) = v1;
            } else {
                *(float2*)(C + (size_t)(rowBase + lr0) * ldc + colC + col) = v0;
                *(float2*)(C + (size_t)(rowBase + lr1) * ldc + colC + col) = v1;
            }
        }
    }
}

// QKV kernel: y 0..3 -> V dense (all rows); y 4..11 -> Q/K gathered (non-reset)
__global__ __launch_bounds__(256) void qkv_gemm_tc(
    const float* __restrict__ bq, const float* __restrict__ bk,
    const float* __restrict__ bv)
{
    const int y = blockIdx.y;
    if (y < 4) {
        const int nc = y * BN;
        tc_gemm_body<false>(g_xt, g_wvt, bv, g_qkv, DIM, QKV_LD,
                            blockIdx.x * BM, nc, 2 * DWM + nc, DIM / BK, BSZ);
    } else {
        const int q  = y - 4;          // 0..7
        const int zz = q >> 2;         // 0=Q, 1=K
        const int nc = (q & 3) * BN;
        const int nrows = g_nrows;
        if (blockIdx.x * BM >= nrows) return;
        const float* Bw = zz ? g_wkt : g_wqt;
        const float* bi = zz ? bk : bq;
        tc_gemm_body<true>(g_xt, Bw, bi, g_qkv, DIM, QKV_LD,
                           blockIdx.x * BM, nc, zz * DWM + nc, DIM / BK, nrows);
    }
}

__global__ __launch_bounds__(256) void out_gemm_tc(
    const float* __restrict__ bo, float* __restrict__ y)
{
    tc_gemm_body<false>(g_att, g_wot, bo, y, DWM, DIM,
                        blockIdx.x * BM, blockIdx.y * BN, blockIdx.y * BN,
                        DWM / BK, BSZ);
}

// ---------------- Attention kernel: one CTA per batch row --------------------
// Reset rows: only freshly-written slot valid -> out = v_new exactly (early exit).
// Output stored tf32-rounded (same rounding point the out-GEMM staging used).
__global__ __launch_bounds__(256) void attn_kernel(
    const float* __restrict__ wmK, const float* __restrict__ wmV,
    const void* __restrict__ validIn,
    const void* __restrict__ resetIn,
    const int* __restrict__ ptrIn)
{
    __shared__ float q_s[DWM];
    __shared__ float att_s[NH][WIN];
    __shared__ unsigned char valid_s[WIN];

    const int b    = blockIdx.x;
    const int tid  = threadIdx.x;   // 256
    const int lane = tid & 31;
    const int warp = tid >> 5;      // 8 warps == 8 heads

    const int mode = bool_mode((const unsigned char*)validIn);
    const bool rs = read_bool(resetIn, b, mode);

    const float* qrow  = g_qkv + (size_t)b * QKV_LD;
    const float* knew  = qrow + DWM;
    const float* vnew  = qrow + 2 * DWM;

    if (rs) {
        float2 v0 = *(const float2*)(vnew + tid * 2);
        v0.x = __uint_as_float(f2tf32(v0.x));
        v0.y = __uint_as_float(f2tf32(v0.y));
        *(float2*)(g_att + (size_t)b * DWM + tid * 2) = v0;
        return;
    }

    const int p = ptrIn[b];
    const float* Kbase = wmK + (size_t)b * WIN * DWM;
    const float* Vbase = wmV + (size_t)b * WIN * DWM;

    for (int i = tid; i < DWM; i += 256) q_s[i] = qrow[i];
    if (tid < WIN)
        valid_s[tid] = read_bool(validIn, (size_t)b * WIN + tid, mode) ? 1 : 0;
    __syncthreads();

    const float NEG_INF = __int_as_float(0xff800000);

    // ---- phase 1: logits (uniform over stored K; slot p patched after) ----
    {
        const int h = warp;
        float2 qv = *(const float2*)(q_s + h * HD + lane * 2);
        const float2* kp = (const float2*)(Kbase + h * HD + lane * 2);
        for (int w0 = 0; w0 < WIN; w0 += 8) {
            float s[8];
            #pragma unroll
            for (int u = 0; u < 8; ++u) {
                float2 kv = __ldcs(kp + (size_t)(w0 + u) * (DWM / 2));
                s[u] = kv.x * qv.x + kv.y * qv.y;
            }
            #pragma unroll
            for (int u = 0; u < 8; ++u) {
                #pragma unroll
                for (int o = 16; o > 0; o >>= 1)
                    s[u] += __shfl_xor_sync(0xffffffffu, s[u], o);
            }
            if (lane == 0) {
                #pragma unroll
                for (int u = 0; u < 8; ++u) {
                    int w = w0 + u;
                    bool val = (valid_s[w] != 0);
                    att_s[h][w] = val ? s[u] * ATT_SCALE : NEG_INF;
                }
            }
        }
        {
            float2 kv = *(const float2*)(knew + h * HD + lane * 2);
            float s = kv.x * qv.x + kv.y * qv.y;
            #pragma unroll
            for (int o = 16; o > 0; o >>= 1)
                s += __shfl_xor_sync(0xffffffffu, s, o);
            if (lane == 0) att_s[h][p] = s * ATT_SCALE;
        }
    }
    __syncthreads();

    // ---- phase 2: per-head softmax (warp h) ----
    {
        const int h = warp;
        float e[8];
        float m = NEG_INF;
        #pragma unroll
        for (int j = 0; j < 8; ++j) {
            e[j] = att_s[h][lane + 32 * j];
            m = fmaxf(m, e[j]);
        }
        #pragma unroll
        for (int o = 16; o > 0; o >>= 1)
            m = fmaxf(m, __shfl_xor_sync(0xffffffffu, m, o));
        float sum = 0.f;
        #pragma unroll
        for (int j = 0; j < 8; ++j) {
            e[j] = __expf(e[j] - m);
            sum += e[j];
        }
        #pragma unroll
        for (int o = 16; o > 0; o >>= 1)
            sum += __shfl_xor_sync(0xffffffffu, sum, o);
        float inv = (sum > 0.f) ? (1.0f / sum) : 0.f;
        #pragma unroll
        for (int j = 0; j < 8; ++j)
            att_s[h][lane + 32 * j] = e[j] * inv;
    }
    __syncthreads();

    // ---- phase 3: AV, uniform over stored V; correction for slot p ----
    {
        const int d = tid * 2;
        const int h = tid >> 5;
        float ax = 0.f, ay = 0.f;
        const float2* vp = (const float2*)(Vbase + d);
        for (int w0 = 0; w0 < WIN; w0 += 8) {
            float2 vv[8];
            #pragma unroll
            for (int u = 0; u < 8; ++u)
                vv[u] = __ldcs(vp + (size_t)(w0 + u) * (DWM / 2));
            #pragma unroll
            for (int u = 0; u < 8; ++u) {
                float pw = att_s[h][w0 + u];
                ax = fmaf(pw, vv[u].x, ax);
                ay = fmaf(pw, vv[u].y, ay);
            }
        }
        {
            float2 vold = *(const float2*)(Vbase + (size_t)p * DWM + d);
            float2 vn   = *(const float2*)(vnew + d);
            float pw = att_s[h][p];
            ax = fmaf(pw, vn.x - vold.x, ax);
            ay = fmaf(pw, vn.y - vold.y, ay);
        }
        float2 o;
        o.x = __uint_as_float(f2tf32(ax));
        o.y = __uint_as_float(f2tf32(ay));
        *(float2*)(g_att + (size_t)b * DWM + d) = o;
    }
}

// ---------------- launcher ---------------------------------------------------
extern "C" void kernel_launch(void* const* d_in, const int* in_sizes, int n_in,
                              void* d_out, int out_size)
{
    const float* x     = (const float*)d_in[0];
    const void*  reset = d_in[1];
    const float* wmK   = (const float*)d_in[2];
    const float* wmV   = (const float*)d_in[3];
    const void*  valid = d_in[4];
    const int*   ptr   = (const int*)d_in[5];
    const float* Wq    = (const float*)d_in[6];
    const float* bq    = (const float*)d_in[7];
    const float* Wk    = (const float*)d_in[8];
    const float* bk    = (const float*)d_in[9];
    const float* Wv    = (const float*)d_in[10];
    const float* bv    = (const float*)d_in[11];
    const float* Wo    = (const float*)d_in[12];
    const float* bo    = (const float*)d_in[13];
    float*       y     = (float*)d_out;

    // opt-in to 128 KB dynamic smem (host attribute set; idempotent)
    cudaFuncSetAttribute(qkv_gemm_tc, cudaFuncAttributeMaxDynamicSharedMemorySize, TCSM_BYTES);
    cudaFuncSetAttribute(out_gemm_tc, cudaFuncAttributeMaxDynamicSharedMemorySize, TCSM_BYTES);

    compact_kernel<<<1, 1024>>>(reset, valid);
    convert_kernel<<<2048, 256>>>(x, Wq, Wk, Wv, Wo);

    dim3 gQKV(BSZ / BM, 12);            // 16 x 12; Q/K tail tiles self-disable
    qkv_gemm_tc<<<gQKV, 256, TCSM_BYTES>>>(bq, bk, bv);

    attn_kernel<<<BSZ, 256>>>(wmK, wmV, valid, reset, ptr);

    dim3 gOut(BSZ / BM, DIM / BN);      // 16 x 8 = 128 CTAs
    out_gemm_tc<<<gOut, 256, TCSM_BYTES>>>(bo, y);
}

// round 15
// speedup vs baseline: 1.1794x; 1.0154x over previous
#include <cuda_runtime.h>
#include <cstdint>

// Problem constants
#define BSZ   2048
#define DIM   1024
#define DWM   512
#define WIN   256
#define NH    8
#define HD    64
#define QKV_LD 1536
#define ATT_SCALE 0.125f

// Scratch (device globals: allocation-free rule)
__device__ float g_qkv[(size_t)BSZ * QKV_LD];   // 12 MB
__device__ float g_att[(size_t)BSZ * DWM];      // 4 MB (tf32-valued)
__device__ int   g_rows[BSZ];                   // permutation: non-reset first
__device__ int   g_nrows;                       // count of non-reset rows
// tf32-pre-rounded operands
__device__ float g_xt [(size_t)BSZ * DIM];      // 8 MB
__device__ float g_wqt[(size_t)DWM * DIM];      // 2 MB
__device__ float g_wkt[(size_t)DWM * DIM];
__device__ float g_wvt[(size_t)DWM * DIM];
__device__ float g_wot[(size_t)DIM * DWM];

// ---------------- bool dtype helpers ------------------------------------------
__device__ __forceinline__ int bool_mode(const unsigned char* valid)
{
    unsigned char b0 = valid[0], b1 = valid[1];
    return (b0 == 0) ? 2 : (b1 != 0 ? 0 : 1);   // 0=u8, 1=i32, 2=f32
}
__device__ __forceinline__ bool read_bool(const void* p, long idx, int mode)
{
    if (mode == 1) return ((const int*)p)[idx] != 0;
    if (mode == 2) return ((const float*)p)[idx] != 0.0f;
    return ((const unsigned char*)p)[idx] != 0;
}

// ---------------- tf32 helpers ------------------------------------------------
__device__ __forceinline__ uint32_t f2tf32(float f) {
    uint32_t u;
    asm("cvt.rna.tf32.f32 %0, %1;" : "=r"(u) : "f"(f));
    return u;
}
__device__ __forceinline__ void mma_tf32(float* d, const uint32_t* a, const uint32_t* b) {
    asm volatile(
        "mma.sync.aligned.m16n8k8.row.col.f32.tf32.tf32.f32 "
        "{%0,%1,%2,%3},{%4,%5,%6,%7},{%8,%9},{%0,%1,%2,%3};\n"
        : "+f"(d[0]), "+f"(d[1]), "+f"(d[2]), "+f"(d[3])
        : "r"(a[0]), "r"(a[1]), "r"(a[2]), "r"(a[3]), "r"(b[0]), "r"(b[1]));
}
__device__ __forceinline__ void cp16(uint32_t dst_smem, const void* src) {
    asm volatile("cp.async.cg.shared.global [%0], [%1], 16;"
                 :: "r"(dst_smem), "l"(src));
}

// ---------------- convert + compaction (fused, one launch) --------------------
// Blocks 0..2047: pre-round x + weights to tf32 values.
// Block 2048: build g_rows permutation (non-reset rows first, reset rows after)
//             + g_nrows, via a 256-thread scan (8 elements each).
#define X_F4  (BSZ * DIM / 4)     // 524288
#define W_F4  (DWM * DIM / 4)     // 131072
__global__ __launch_bounds__(256) void convert_kernel(
    const float* __restrict__ x,  const float* __restrict__ wq,
    const float* __restrict__ wk, const float* __restrict__ wv,
    const float* __restrict__ wo,
    const void* __restrict__ resetIn, const void* __restrict__ validIn)
{
    if (blockIdx.x == 2048) {
        // ---- compaction ----
        __shared__ int wsum_s[8];
        __shared__ int total_s;
        const int t    = threadIdx.x;
        const int lane = t & 31;
        const int wid  = t >> 5;
        const int mode = bool_mode((const unsigned char*)validIn);

        bool nr[8];
        int cnt = 0;
        #pragma unroll
        for (int j = 0; j < 8; ++j) {
            nr[j] = !read_bool(resetIn, 8 * t + j, mode);
            cnt += (int)nr[j];
        }
        // warp inclusive scan
        int incl = cnt;
        #pragma unroll
        for (int o = 1; o < 32; o <<= 1) {
            int v = __shfl_up_sync(0xffffffffu, incl, o);
            if (lane >= o) incl += v;
        }
        if (lane == 31) wsum_s[wid] = incl;
        __syncthreads();
        if (t < 8) {
            int v = wsum_s[t];
            #pragma unroll
            for (int o = 1; o < 8; o <<= 1) {
                int u = __shfl_up_sync(0xffu, v, o);
                if (t >= o) v += u;
            }
            wsum_s[t] = v;
            if (t == 7) total_s = v;
        }
        __syncthreads();
        int base = (wid > 0) ? wsum_s[wid - 1] : 0;
        int excl = base + incl - cnt;          // non-reset before element 8t
        const int total = total_s;
        int posn = excl;
        int posr = total + (8 * t - excl);     // reset prefix = 8t - excl
        #pragma unroll
        for (int j = 0; j < 8; ++j) {
            if (nr[j]) g_rows[posn++] = 8 * t + j;
            else       g_rows[posr++] = 8 * t + j;
        }
        if (t == 0) g_nrows = total;
        return;
    }

    // ---- conversion ----
    const int gid = blockIdx.x * 256 + threadIdx.x;
    #pragma unroll
    for (int rep = 0; rep < 2; ++rep) {
        int i = gid + rep * 524288;
        const float4* s; uint4* d; int off;
        if (i < X_F4)                 { s = (const float4*)x;  d = (uint4*)g_xt;  off = i; }
        else if (i < X_F4 + W_F4)     { s = (const float4*)wq; d = (uint4*)g_wqt; off = i - X_F4; }
        else if (i < X_F4 + 2*W_F4)   { s = (const float4*)wk; d = (uint4*)g_wkt; off = i - X_F4 - W_F4; }
        else if (i < X_F4 + 3*W_F4)   { s = (const float4*)wv; d = (uint4*)g_wvt; off = i - X_F4 - 2*W_F4; }
        else                          { s = (const float4*)wo; d = (uint4*)g_wot; off = i - X_F4 - 3*W_F4; }
        float4 v = s[off];
        uint4 t;
        t.x = f2tf32(v.x); t.y = f2tf32(v.y); t.z = f2tf32(v.z); t.w = f2tf32(v.w);
        d[off] = t;
    }
}

// ===================== tf32 mma.sync GEMM, 4-stage cp.async ===================
// C[m,n] = sum_k A[m,k]*B[n,k] + bias[n]; A,B pre-rounded to tf32 values.
// CTA tile 128x128, K-tile 32, 256 threads = 8 warps (2m x 4n), warp tile 64x32.
#define BM 128
#define BN 128
#define BK 32
#define NSTAGE 4
#define A_FL (BM * BK)                    // 4096 floats
#define B_FL (BN * BK)                    // 4096
#define STAGE_FLOATS (A_FL + B_FL)        // 8192
#define STAGE_BYTES  (STAGE_FLOATS * 4)   // 32768
#define TCSM_BYTES   (NSTAGE * STAGE_BYTES)  // 131072 (opt-in)

template<bool GATHER>
__device__ __forceinline__ void tc_gemm_body(
    const float* __restrict__ A, const float* __restrict__ Bw,
    const float* __restrict__ bias, float* __restrict__ C,
    int K, int ldc, int rowBase, int colB, int colC, int niter, int nrows)
{
    extern __shared__ float smem[];
    __shared__ int ridx_s[BM];

    const int tid  = threadIdx.x;
    const int lane = tid & 31;
    const int warp = tid >> 5;
    const int g    = lane >> 2;          // 0..7
    const int tg   = lane & 3;           // 0..3
    const int wm   = (warp >> 2) * 64;   // 0,64
    const int wn   = (warp & 3) * 32;    // 0,32,64,96

    if (GATHER) {
        if (tid < BM) {
            int rr = rowBase + tid;
            ridx_s[tid] = (rr < nrows) ? g_rows[rr] : 0;
        }
        __syncthreads();
    }

    const float* Bbase = Bw + (size_t)colB * K;
    const uint32_t smem_u = (uint32_t)__cvta_generic_to_shared(smem);

    float acc[4][4][4];
    #pragma unroll
    for (int mt = 0; mt < 4; ++mt)
        #pragma unroll
        for (int nt = 0; nt < 4; ++nt)
            #pragma unroll
            for (int r = 0; r < 4; ++r) acc[mt][nt][r] = 0.f;

    auto arow = [&](int row) -> const float* {
        int rr = GATHER ? ridx_s[row] : (rowBase + row);
        return A + (size_t)rr * K;
    };
    auto issue_tile = [&](int stage, int ko) {
        uint32_t abase = smem_u + stage * STAGE_BYTES;
        uint32_t bbase = abase + A_FL * 4;
        #pragma unroll
        for (int i = 0; i < 4; ++i) {
            int idx = tid + (i << 8), row = idx >> 3, q = idx & 7;
            uint32_t soff = (uint32_t)(row * BK + ((q ^ (row & 7)) << 2)) * 4u;
            cp16(abase + soff, arow(row) + ko + (q << 2));
            cp16(bbase + soff, Bbase + (size_t)row * K + ko + (q << 2));
        }
        asm volatile("cp.async.commit_group;");
    };

    const int npro = (niter < NSTAGE - 1) ? niter : (NSTAGE - 1);
    for (int s = 0; s < npro; ++s) issue_tile(s, s * BK);

    for (int it = 0; it < niter; ++it) {
        int allow = niter - it - 1;
        if (allow > NSTAGE - 2) allow = NSTAGE - 2;
        if (allow == 2)      asm volatile("cp.async.wait_group 2;");
        else if (allow == 1) asm volatile("cp.async.wait_group 1;");
        else                 asm volatile("cp.async.wait_group 0;");
        __syncthreads();

        if (it + NSTAGE - 1 < niter)
            issue_tile((it + NSTAGE - 1) & (NSTAGE - 1), (it + NSTAGE - 1) * BK);

        const uint32_t* Abuf = (const uint32_t*)(smem + (it & (NSTAGE - 1)) * STAGE_FLOATS);
        const uint32_t* Bbuf = Abuf + A_FL;
        #pragma unroll
        for (int ks = 0; ks < 4; ++ks) {
            uint32_t af[4][4], bf[4][2];
            const int g0 = ((2 * ks) ^ g) << 2;
            const int g1 = ((2 * ks + 1) ^ g) << 2;
            #pragma unroll
            for (int mt = 0; mt < 4; ++mt) {
                int r0 = wm + mt * 16 + g;
                int r1 = r0 + 8;
                af[mt][0] = Abuf[r0 * BK + g0 + tg];
                af[mt][1] = Abuf[r1 * BK + g0 + tg];
                af[mt][2] = Abuf[r0 * BK + g1 + tg];
                af[mt][3] = Abuf[r1 * BK + g1 + tg];
            }
            #pragma unroll
            for (int nt = 0; nt < 4; ++nt) {
                int n = wn + nt * 8 + g;
                bf[nt][0] = Bbuf[n * BK + g0 + tg];
                bf[nt][1] = Bbuf[n * BK + g1 + tg];
            }
            #pragma unroll
            for (int mt = 0; mt < 4; ++mt)
                #pragma unroll
                for (int nt = 0; nt < 4; ++nt)
                    mma_tf32(acc[mt][nt], af[mt], bf[nt]);
        }
    }

    // ---- epilogue: C = acc + bias ----
    #pragma unroll
    for (int mt = 0; mt < 4; ++mt) {
        #pragma unroll
        for (int nt = 0; nt < 4; ++nt) {
            int lr0 = wm + mt * 16 + g;
            int lr1 = lr0 + 8;
            int col = wn + nt * 8 + tg * 2;
            float b0 = bias[colB + col], b1 = bias[colB + col + 1];
            float2 v0 = make_float2(acc[mt][nt][0] + b0, acc[mt][nt][1] + b1);
            float2 v1 = make_float2(acc[mt][nt][2] + b0, acc[mt][nt][3] + b1);
            if (GATHER) {
                if (rowBase + lr0 < nrows)
                    *(float2*)(C + (size_t)ridx_s[lr0] * ldc + colC + col) = v0;
                if (rowBase + lr1 < nrows)
                    *(float2*)(C + (size_t)ridx_s[lr1] * ldc + colC + col) = v1;
            } else {
                *(float2*)(C + (size_t)(rowBase + lr0) * ldc + colC + col) = v0;
                *(float2*)(C + (size_t)(rowBase + lr1) * ldc + colC + col) = v1;
            }
        }
    }
}

// QKV kernel: y 0..3 -> V dense (all rows); y 4..11 -> Q/K gathered (non-reset)
__global__ __launch_bounds__(256) void qkv_gemm_tc(
    const float* __restrict__ bq, const float* __restrict__ bk,
    const float* __restrict__ bv)
{
    const int y = blockIdx.y;
    if (y < 4) {
        const int nc = y * BN;
        tc_gemm_body<false>(g_xt, g_wvt, bv, g_qkv, DIM, QKV_LD,
                            blockIdx.x * BM, nc, 2 * DWM + nc, DIM / BK, BSZ);
    } else {
        const int q  = y - 4;          // 0..7
        const int zz = q >> 2;         // 0=Q, 1=K
        const int nc = (q & 3) * BN;
        const int nrows = g_nrows;
        if (blockIdx.x * BM >= nrows) return;
        const float* Bw = zz ? g_wkt : g_wqt;
        const float* bi = zz ? bk : bq;
        tc_gemm_body<true>(g_xt, Bw, bi, g_qkv, DIM, QKV_LD,
                           blockIdx.x * BM, nc, zz * DWM + nc, DIM / BK, nrows);
    }
}

__global__ __launch_bounds__(256) void out_gemm_tc(
    const float* __restrict__ bo, float* __restrict__ y)
{
    tc_gemm_body<false>(g_att, g_wot, bo, y, DWM, DIM,
                        blockIdx.x * BM, blockIdx.y * BN, blockIdx.y * BN,
                        DWM / BK, BSZ);
}

// ---------------- Attention kernel: one CTA per (permuted) batch row ----------
// blockIdx.x < g_nrows  -> heavy row b = g_rows[bid] (non-reset), full path.
// blockIdx.x >= g_nrows -> reset row: out = v_new exactly (early exit).
// Heavy rows occupy the low block ids -> scheduled first; trivial CTAs tail.
__global__ __launch_bounds__(256) void attn_kernel(
    const float* __restrict__ wmK, const float* __restrict__ wmV,
    const void* __restrict__ validIn,
    const int* __restrict__ ptrIn)
{
    __shared__ float q_s[DWM];
    __shared__ float att_s[NH][WIN];
    __shared__ unsigned char valid_s[WIN];

    const int bid  = blockIdx.x;
    const int tid  = threadIdx.x;   // 256
    const int lane = tid & 31;
    const int warp = tid >> 5;      // 8 warps == 8 heads

    const int b  = g_rows[bid];
    const bool rs = (bid >= g_nrows);

    const float* qrow  = g_qkv + (size_t)b * QKV_LD;
    const float* knew  = qrow + DWM;
    const float* vnew  = qrow + 2 * DWM;

    if (rs) {
        float2 v0 = *(const float2*)(vnew + tid * 2);
        v0.x = __uint_as_float(f2tf32(v0.x));
        v0.y = __uint_as_float(f2tf32(v0.y));
        *(float2*)(g_att + (size_t)b * DWM + tid * 2) = v0;
        return;
    }

    const int mode = bool_mode((const unsigned char*)validIn);
    const int p = ptrIn[b];
    const float* Kbase = wmK + (size_t)b * WIN * DWM;
    const float* Vbase = wmV + (size_t)b * WIN * DWM;

    for (int i = tid; i < DWM; i += 256) q_s[i] = qrow[i];
    if (tid < WIN)
        valid_s[tid] = read_bool(validIn, (size_t)b * WIN + tid, mode) ? 1 : 0;
    __syncthreads();

    const float NEG_INF = __int_as_float(0xff800000);

    // ---- phase 1: logits (uniform over stored K; slot p patched after) ----
    {
        const int h = warp;
        float2 qv = *(const float2*)(q_s + h * HD + lane * 2);
        const float2* kp = (const float2*)(Kbase + h * HD + lane * 2);
        for (int w0 = 0; w0 < WIN; w0 += 8) {
            float s[8];
            #pragma unroll
            for (int u = 0; u < 8; ++u) {
                float2 kv = __ldcs(kp + (size_t)(w0 + u) * (DWM / 2));
                s[u] = kv.x * qv.x + kv.y * qv.y;
            }
            #pragma unroll
            for (int u = 0; u < 8; ++u) {
                #pragma unroll
                for (int o = 16; o > 0; o >>= 1)
                    s[u] += __shfl_xor_sync(0xffffffffu, s[u], o);
            }
            if (lane == 0) {
                #pragma unroll
                for (int u = 0; u < 8; ++u) {
                    int w = w0 + u;
                    bool val = (valid_s[w] != 0);
                    att_s[h][w] = val ? s[u] * ATT_SCALE : NEG_INF;
                }
            }
        }
        {
            float2 kv = *(const float2*)(knew + h * HD + lane * 2);
            float s = kv.x * qv.x + kv.y * qv.y;
            #pragma unroll
            for (int o = 16; o > 0; o >>= 1)
                s += __shfl_xor_sync(0xffffffffu, s, o);
            if (lane == 0) att_s[h][p] = s * ATT_SCALE;
        }
    }
    __syncthreads();

    // ---- phase 2: per-head softmax (warp h) ----
    {
        const int h = warp;
        float e[8];
        float m = NEG_INF;
        #pragma unroll
        for (int j = 0; j < 8; ++j) {
            e[j] = att_s[h][lane + 32 * j];
            m = fmaxf(m, e[j]);
        }
        #pragma unroll
        for (int o = 16; o > 0; o >>= 1)
            m = fmaxf(m, __shfl_xor_sync(0xffffffffu, m, o));
        float sum = 0.f;
        #pragma unroll
        for (int j = 0; j < 8; ++j) {
            e[j] = __expf(e[j] - m);
            sum += e[j];
        }
        #pragma unroll
        for (int o = 16; o > 0; o >>= 1)
            sum += __shfl_xor_sync(0xffffffffu, sum, o);
        float inv = (sum > 0.f) ? (1.0f / sum) : 0.f;
        #pragma unroll
        for (int j = 0; j < 8; ++j)
            att_s[h][lane + 32 * j] = e[j] * inv;
    }
    __syncthreads();

    // ---- phase 3: AV, uniform over stored V; correction for slot p ----
    {
        const int d = tid * 2;
        const int h = tid >> 5;
        float ax = 0.f, ay = 0.f;
        const float2* vp = (const float2*)(Vbase + d);
        for (int w0 = 0; w0 < WIN; w0 += 8) {
            float2 vv[8];
            #pragma unroll
            for (int u = 0; u < 8; ++u)
                vv[u] = __ldcs(vp + (size_t)(w0 + u) * (DWM / 2));
            #pragma unroll
            for (int u = 0; u < 8; ++u) {
                float pw = att_s[h][w0 + u];
                ax = fmaf(pw, vv[u].x, ax);
                ay = fmaf(pw, vv[u].y, ay);
            }
        }
        {
            float2 vold = *(const float2*)(Vbase + (size_t)p * DWM + d);
            float2 vn   = *(const float2*)(vnew + d);
            float pw = att_s[h][p];
            ax = fmaf(pw, vn.x - vold.x, ax);
            ay = fmaf(pw, vn.y - vold.y, ay);
        }
        float2 o;
        o.x = __uint_as_float(f2tf32(ax));
        o.y = __uint_as_float(f2tf32(ay));
        *(float2*)(g_att + (size_t)b * DWM + d) = o;
    }
}

// ---------------- launcher ---------------------------------------------------
extern "C" void kernel_launch(void* const* d_in, const int* in_sizes, int n_in,
                              void* d_out, int out_size)
{
    const float* x     = (const float*)d_in[0];
    const void*  reset = d_in[1];
    const float* wmK   = (const float*)d_in[2];
    const float* wmV   = (const float*)d_in[3];
    const void*  valid = d_in[4];
    const int*   ptr   = (const int*)d_in[5];
    const float* Wq    = (const float*)d_in[6];
    const float* bq    = (const float*)d_in[7];
    const float* Wk    = (const float*)d_in[8];
    const float* bk    = (const float*)d_in[9];
    const float* Wv    = (const float*)d_in[10];
    const float* bv    = (const float*)d_in[11];
    const float* Wo    = (const float*)d_in[12];
    const float* bo    = (const float*)d_in[13];
    float*       y     = (float*)d_out;

    // opt-in to 128 KB dynamic smem (host attribute set; idempotent)
    cudaFuncSetAttribute(qkv_gemm_tc, cudaFuncAttributeMaxDynamicSharedMemorySize, TCSM_BYTES);
    cudaFuncSetAttribute(out_gemm_tc, cudaFuncAttributeMaxDynamicSharedMemorySize, TCSM_BYTES);

    // fused: tf32 pre-round (blocks 0..2047) + row compaction (block 2048)
    convert_kernel<<<2049, 256>>>(x, Wq, Wk, Wv, Wo, reset, valid);

    dim3 gQKV(BSZ / BM, 12);            // 16 x 12; Q/K tail tiles self-disable
    qkv_gemm_tc<<<gQKV, 256, TCSM_BYTES>>>(bq, bk, bv);

    attn_kernel<<<BSZ, 256>>>(wmK, wmV, valid, ptr);

    dim3 gOut(BSZ / BM, DIM / BN);      // 16 x 8 = 128 CTAs
    out_gemm_tc<<<gOut, 256, TCSM_BYTES>>>(bo, y);
}

// round 16
// speedup vs baseline: 1.2096x; 1.0256x over previous
#include <cuda_runtime.h>
#include <cstdint>

// Problem constants
#define BSZ   2048
#define DIM   1024
#define DWM   512
#define WIN   256
#define NH    8
#define HD    64
#define QKV_LD 1536
#define ATT_SCALE 0.125f

// Scratch (device globals: allocation-free rule)
__device__ float g_qkv[(size_t)BSZ * QKV_LD];   // 12 MB
__device__ float g_att[(size_t)BSZ * DWM];      // 4 MB (tf32-valued)
__device__ int   g_rows[BSZ];                   // permutation: non-reset first
__device__ int   g_nrows;                       // count of non-reset rows
// tf32-pre-rounded operands
__device__ float g_xt [(size_t)BSZ * DIM];      // 8 MB
__device__ float g_wqt[(size_t)DWM * DIM];      // 2 MB
__device__ float g_wkt[(size_t)DWM * DIM];
__device__ float g_wvt[(size_t)DWM * DIM];
__device__ float g_wot[(size_t)DIM * DWM];

// ---------------- bool dtype helpers ------------------------------------------
__device__ __forceinline__ int bool_mode(const unsigned char* valid)
{
    unsigned char b0 = valid[0], b1 = valid[1];
    return (b0 == 0) ? 2 : (b1 != 0 ? 0 : 1);   // 0=u8, 1=i32, 2=f32
}
__device__ __forceinline__ bool read_bool(const void* p, long idx, int mode)
{
    if (mode == 1) return ((const int*)p)[idx] != 0;
    if (mode == 2) return ((const float*)p)[idx] != 0.0f;
    return ((const unsigned char*)p)[idx] != 0;
}

// ---------------- tf32 helpers ------------------------------------------------
__device__ __forceinline__ uint32_t f2tf32(float f) {
    uint32_t u;
    asm("cvt.rna.tf32.f32 %0, %1;" : "=r"(u) : "f"(f));
    return u;
}
__device__ __forceinline__ void mma_tf32(float* d, const uint32_t* a, const uint32_t* b) {
    asm volatile(
        "mma.sync.aligned.m16n8k8.row.col.f32.tf32.tf32.f32 "
        "{%0,%1,%2,%3},{%4,%5,%6,%7},{%8,%9},{%0,%1,%2,%3};\n"
        : "+f"(d[0]), "+f"(d[1]), "+f"(d[2]), "+f"(d[3])
        : "r"(a[0]), "r"(a[1]), "r"(a[2]), "r"(a[3]), "r"(b[0]), "r"(b[1]));
}
__device__ __forceinline__ void cp16(uint32_t dst_smem, const void* src) {
    asm volatile("cp.async.cg.shared.global [%0], [%1], 16;"
                 :: "r"(dst_smem), "l"(src));
}

// ---------------- convert + compaction (fused, one launch) --------------------
#define X_F4  (BSZ * DIM / 4)     // 524288
#define W_F4  (DWM * DIM / 4)     // 131072
__global__ __launch_bounds__(256) void convert_kernel(
    const float* __restrict__ x,  const float* __restrict__ wq,
    const float* __restrict__ wk, const float* __restrict__ wv,
    const float* __restrict__ wo,
    const void* __restrict__ resetIn, const void* __restrict__ validIn)
{
    if (blockIdx.x == 2048) {
        // ---- compaction: permutation, non-reset rows first ----
        __shared__ int wsum_s[8];
        __shared__ int total_s;
        const int t    = threadIdx.x;
        const int lane = t & 31;
        const int wid  = t >> 5;
        const int mode = bool_mode((const unsigned char*)validIn);

        bool nr[8];
        int cnt = 0;
        #pragma unroll
        for (int j = 0; j < 8; ++j) {
            nr[j] = !read_bool(resetIn, 8 * t + j, mode);
            cnt += (int)nr[j];
        }
        int incl = cnt;
        #pragma unroll
        for (int o = 1; o < 32; o <<= 1) {
            int v = __shfl_up_sync(0xffffffffu, incl, o);
            if (lane >= o) incl += v;
        }
        if (lane == 31) wsum_s[wid] = incl;
        __syncthreads();
        if (t < 8) {
            int v = wsum_s[t];
            #pragma unroll
            for (int o = 1; o < 8; o <<= 1) {
                int u = __shfl_up_sync(0xffu, v, o);
                if (t >= o) v += u;
            }
            wsum_s[t] = v;
            if (t == 7) total_s = v;
        }
        __syncthreads();
        int base = (wid > 0) ? wsum_s[wid - 1] : 0;
        int excl = base + incl - cnt;
        const int total = total_s;
        int posn = excl;
        int posr = total + (8 * t - excl);
        #pragma unroll
        for (int j = 0; j < 8; ++j) {
            if (nr[j]) g_rows[posn++] = 8 * t + j;
            else       g_rows[posr++] = 8 * t + j;
        }
        if (t == 0) g_nrows = total;
        return;
    }

    // ---- conversion ----
    const int gid = blockIdx.x * 256 + threadIdx.x;
    #pragma unroll
    for (int rep = 0; rep < 2; ++rep) {
        int i = gid + rep * 524288;
        const float4* s; uint4* d; int off;
        if (i < X_F4)                 { s = (const float4*)x;  d = (uint4*)g_xt;  off = i; }
        else if (i < X_F4 + W_F4)     { s = (const float4*)wq; d = (uint4*)g_wqt; off = i - X_F4; }
        else if (i < X_F4 + 2*W_F4)   { s = (const float4*)wk; d = (uint4*)g_wkt; off = i - X_F4 - W_F4; }
        else if (i < X_F4 + 3*W_F4)   { s = (const float4*)wv; d = (uint4*)g_wvt; off = i - X_F4 - 2*W_F4; }
        else                          { s = (const float4*)wo; d = (uint4*)g_wot; off = i - X_F4 - 3*W_F4; }
        float4 v = s[off];
        uint4 t;
        t.x = f2tf32(v.x); t.y = f2tf32(v.y); t.z = f2tf32(v.z); t.w = f2tf32(v.w);
        d[off] = t;
    }
}

// ===================== tf32 mma.sync GEMM, 4-stage cp.async ===================
#define BM 128
#define BN 128
#define BK 32
#define NSTAGE 4
#define A_FL (BM * BK)                    // 4096 floats
#define B_FL (BN * BK)                    // 4096
#define STAGE_FLOATS (A_FL + B_FL)        // 8192
#define STAGE_BYTES  (STAGE_FLOATS * 4)   // 32768
#define TCSM_BYTES   (NSTAGE * STAGE_BYTES)  // 131072 (opt-in)

template<bool GATHER>
__device__ __forceinline__ void tc_gemm_body(
    const float* __restrict__ A, const float* __restrict__ Bw,
    const float* __restrict__ bias, float* __restrict__ C,
    int K, int ldc, int rowBase, int colB, int colC, int niter, int nrows)
{
    extern __shared__ float smem[];
    __shared__ int ridx_s[BM];

    const int tid  = threadIdx.x;
    const int lane = tid & 31;
    const int warp = tid >> 5;
    const int g    = lane >> 2;          // 0..7
    const int tg   = lane & 3;           // 0..3
    const int wm   = (warp >> 2) * 64;   // 0,64
    const int wn   = (warp & 3) * 32;    // 0,32,64,96

    if (GATHER) {
        if (tid < BM) {
            int rr = rowBase + tid;
            ridx_s[tid] = (rr < nrows) ? g_rows[rr] : 0;
        }
        __syncthreads();
    }

    const float* Bbase = Bw + (size_t)colB * K;
    const uint32_t smem_u = (uint32_t)__cvta_generic_to_shared(smem);

    float acc[4][4][4];
    #pragma unroll
    for (int mt = 0; mt < 4; ++mt)
        #pragma unroll
        for (int nt = 0; nt < 4; ++nt)
            #pragma unroll
            for (int r = 0; r < 4; ++r) acc[mt][nt][r] = 0.f;

    auto arow = [&](int row) -> const float* {
        int rr = GATHER ? ridx_s[row] : (rowBase + row);
        return A + (size_t)rr * K;
    };
    auto issue_tile = [&](int stage, int ko) {
        uint32_t abase = smem_u + stage * STAGE_BYTES;
        uint32_t bbase = abase + A_FL * 4;
        #pragma unroll
        for (int i = 0; i < 4; ++i) {
            int idx = tid + (i << 8), row = idx >> 3, q = idx & 7;
            uint32_t soff = (uint32_t)(row * BK + ((q ^ (row & 7)) << 2)) * 4u;
            cp16(abase + soff, arow(row) + ko + (q << 2));
            cp16(bbase + soff, Bbase + (size_t)row * K + ko + (q << 2));
        }
        asm volatile("cp.async.commit_group;");
    };

    const int npro = (niter < NSTAGE - 1) ? niter : (NSTAGE - 1);
    for (int s = 0; s < npro; ++s) issue_tile(s, s * BK);

    for (int it = 0; it < niter; ++it) {
        int allow = niter - it - 1;
        if (allow > NSTAGE - 2) allow = NSTAGE - 2;
        if (allow == 2)      asm volatile("cp.async.wait_group 2;");
        else if (allow == 1) asm volatile("cp.async.wait_group 1;");
        else                 asm volatile("cp.async.wait_group 0;");
        __syncthreads();

        if (it + NSTAGE - 1 < niter)
            issue_tile((it + NSTAGE - 1) & (NSTAGE - 1), (it + NSTAGE - 1) * BK);

        const uint32_t* Abuf = (const uint32_t*)(smem + (it & (NSTAGE - 1)) * STAGE_FLOATS);
        const uint32_t* Bbuf = Abuf + A_FL;
        #pragma unroll
        for (int ks = 0; ks < 4; ++ks) {
            uint32_t af[4][4], bf[4][2];
            const int g0 = ((2 * ks) ^ g) << 2;
            const int g1 = ((2 * ks + 1) ^ g) << 2;
            #pragma unroll
            for (int mt = 0; mt < 4; ++mt) {
                int r0 = wm + mt * 16 + g;
                int r1 = r0 + 8;
                af[mt][0] = Abuf[r0 * BK + g0 + tg];
                af[mt][1] = Abuf[r1 * BK + g0 + tg];
                af[mt][2] = Abuf[r0 * BK + g1 + tg];
                af[mt][3] = Abuf[r1 * BK + g1 + tg];
            }
            #pragma unroll
            for (int nt = 0; nt < 4; ++nt) {
                int n = wn + nt * 8 + g;
                bf[nt][0] = Bbuf[n * BK + g0 + tg];
                bf[nt][1] = Bbuf[n * BK + g1 + tg];
            }
            #pragma unroll
            for (int mt = 0; mt < 4; ++mt)
                #pragma unroll
                for (int nt = 0; nt < 4; ++nt)
                    mma_tf32(acc[mt][nt], af[mt], bf[nt]);
        }
    }

    // ---- epilogue: C = acc + bias ----
    #pragma unroll
    for (int mt = 0; mt < 4; ++mt) {
        #pragma unroll
        for (int nt = 0; nt < 4; ++nt) {
            int lr0 = wm + mt * 16 + g;
            int lr1 = lr0 + 8;
            int col = wn + nt * 8 + tg * 2;
            float b0 = bias[colB + col], b1 = bias[colB + col + 1];
            float2 v0 = make_float2(acc[mt][nt][0] + b0, acc[mt][nt][1] + b1);
            float2 v1 = make_float2(acc[mt][nt][2] + b0, acc[mt][nt][3] + b1);
            if (GATHER) {
                if (rowBase + lr0 < nrows)
                    *(float2*)(C + (size_t)ridx_s[lr0] * ldc + colC + col) = v0;
                if (rowBase + lr1 < nrows)
                    *(float2*)(C + (size_t)ridx_s[lr1] * ldc + colC + col) = v1;
            } else {
                *(float2*)(C + (size_t)(rowBase + lr0) * ldc + colC + col) = v0;
                *(float2*)(C + (size_t)(rowBase + lr1) * ldc + colC + col) = v1;
            }
        }
    }
}

// QKV kernel: y 0..3 -> V dense (all rows); y 4..11 -> Q/K gathered (non-reset)
__global__ __launch_bounds__(256) void qkv_gemm_tc(
    const float* __restrict__ bq, const float* __restrict__ bk,
    const float* __restrict__ bv)
{
    const int y = blockIdx.y;
    if (y < 4) {
        const int nc = y * BN;
        tc_gemm_body<false>(g_xt, g_wvt, bv, g_qkv, DIM, QKV_LD,
                            blockIdx.x * BM, nc, 2 * DWM + nc, DIM / BK, BSZ);
    } else {
        const int q  = y - 4;          // 0..7
        const int zz = q >> 2;         // 0=Q, 1=K
        const int nc = (q & 3) * BN;
        const int nrows = g_nrows;
        if (blockIdx.x * BM >= nrows) return;
        const float* Bw = zz ? g_wkt : g_wqt;
        const float* bi = zz ? bk : bq;
        tc_gemm_body<true>(g_xt, Bw, bi, g_qkv, DIM, QKV_LD,
                           blockIdx.x * BM, nc, zz * DWM + nc, DIM / BK, nrows);
    }
}

__global__ __launch_bounds__(256) void out_gemm_tc(
    const float* __restrict__ bo, float* __restrict__ y)
{
    tc_gemm_body<false>(g_att, g_wot, bo, y, DWM, DIM,
                        blockIdx.x * BM, blockIdx.y * BN, blockIdx.y * BN,
                        DWM / BK, BSZ);
}

// ---------------- Attention kernel: one CTA per (permuted) batch row ----------
// blockIdx.x < g_nrows  -> heavy row b = g_rows[bid] (non-reset), full path.
// blockIdx.x >= g_nrows -> reset row: out = v_new exactly (early exit).
// Unroll 16 in both streaming phases for deeper MLP (same access pattern).
__global__ __launch_bounds__(256) void attn_kernel(
    const float* __restrict__ wmK, const float* __restrict__ wmV,
    const void* __restrict__ validIn,
    const int* __restrict__ ptrIn)
{
    __shared__ float q_s[DWM];
    __shared__ float att_s[NH][WIN];
    __shared__ unsigned char valid_s[WIN];

    const int bid  = blockIdx.x;
    const int tid  = threadIdx.x;   // 256
    const int lane = tid & 31;
    const int warp = tid >> 5;      // 8 warps == 8 heads

    const int b  = g_rows[bid];
    const bool rs = (bid >= g_nrows);

    const float* qrow  = g_qkv + (size_t)b * QKV_LD;
    const float* knew  = qrow + DWM;
    const float* vnew  = qrow + 2 * DWM;

    if (rs) {
        float2 v0 = *(const float2*)(vnew + tid * 2);
        v0.x = __uint_as_float(f2tf32(v0.x));
        v0.y = __uint_as_float(f2tf32(v0.y));
        *(float2*)(g_att + (size_t)b * DWM + tid * 2) = v0;
        return;
    }

    const int mode = bool_mode((const unsigned char*)validIn);
    const int p = ptrIn[b];
    const float* Kbase = wmK + (size_t)b * WIN * DWM;
    const float* Vbase = wmV + (size_t)b * WIN * DWM;

    for (int i = tid; i < DWM; i += 256) q_s[i] = qrow[i];
    if (tid < WIN)
        valid_s[tid] = read_bool(validIn, (size_t)b * WIN + tid, mode) ? 1 : 0;
    __syncthreads();

    const float NEG_INF = __int_as_float(0xff800000);

    // ---- phase 1: logits, unroll 16 (uniform over stored K; p patched) ----
    {
        const int h = warp;
        float2 qv = *(const float2*)(q_s + h * HD + lane * 2);
        const float2* kp = (const float2*)(Kbase + h * HD + lane * 2);
        for (int w0 = 0; w0 < WIN; w0 += 16) {
            float s[16];
            #pragma unroll
            for (int u = 0; u < 16; ++u) {
                float2 kv = __ldcs(kp + (size_t)(w0 + u) * (DWM / 2));
                s[u] = kv.x * qv.x + kv.y * qv.y;
            }
            #pragma unroll
            for (int u = 0; u < 16; ++u) {
                #pragma unroll
                for (int o = 16; o > 0; o >>= 1)
                    s[u] += __shfl_xor_sync(0xffffffffu, s[u], o);
            }
            if (lane == 0) {
                #pragma unroll
                for (int u = 0; u < 16; ++u) {
                    int w = w0 + u;
                    bool val = (valid_s[w] != 0);
                    att_s[h][w] = val ? s[u] * ATT_SCALE : NEG_INF;
                }
            }
        }
        {
            float2 kv = *(const float2*)(knew + h * HD + lane * 2);
            float s = kv.x * qv.x + kv.y * qv.y;
            #pragma unroll
            for (int o = 16; o > 0; o >>= 1)
                s += __shfl_xor_sync(0xffffffffu, s, o);
            if (lane == 0) att_s[h][p] = s * ATT_SCALE;
        }
    }
    __syncthreads();

    // prefetch first V batch before softmax (independent of att_s values)
    const int d = tid * 2;
    const int h3 = tid >> 5;
    const float2* vp = (const float2*)(Vbase + d);
    float2 vv0[16];
    #pragma unroll
    for (int u = 0; u < 16; ++u)
        vv0[u] = __ldcs(vp + (size_t)u * (DWM / 2));

    // ---- phase 2: per-head softmax (warp h) ----
    {
        const int h = warp;
        float e[8];
        float m = NEG_INF;
        #pragma unroll
        for (int j = 0; j < 8; ++j) {
            e[j] = att_s[h][lane + 32 * j];
            m = fmaxf(m, e[j]);
        }
        #pragma unroll
        for (int o = 16; o > 0; o >>= 1)
            m = fmaxf(m, __shfl_xor_sync(0xffffffffu, m, o));
        float sum = 0.f;
        #pragma unroll
        for (int j = 0; j < 8; ++j) {
            e[j] = __expf(e[j] - m);
            sum += e[j];
        }
        #pragma unroll
        for (int o = 16; o > 0; o >>= 1)
            sum += __shfl_xor_sync(0xffffffffu, sum, o);
        float inv = (sum > 0.f) ? (1.0f / sum) : 0.f;
        #pragma unroll
        for (int j = 0; j < 8; ++j)
            att_s[h][lane + 32 * j] = e[j] * inv;
    }
    __syncthreads();

    // ---- phase 3: AV, unroll 16; correction for slot p ----
    {
        float ax = 0.f, ay = 0.f;
        #pragma unroll
        for (int u = 0; u < 16; ++u) {
            float pw = att_s[h3][u];
            ax = fmaf(pw, vv0[u].x, ax);
            ay = fmaf(pw, vv0[u].y, ay);
        }
        for (int w0 = 16; w0 < WIN; w0 += 16) {
            float2 vv[16];
            #pragma unroll
            for (int u = 0; u < 16; ++u)
                vv[u] = __ldcs(vp + (size_t)(w0 + u) * (DWM / 2));
            #pragma unroll
            for (int u = 0; u < 16; ++u) {
                float pw = att_s[h3][w0 + u];
                ax = fmaf(pw, vv[u].x, ax);
                ay = fmaf(pw, vv[u].y, ay);
            }
        }
        {
            float2 vold = *(const float2*)(Vbase + (size_t)p * DWM + d);
            float2 vn   = *(const float2*)(vnew + d);
            float pw = att_s[h3][p];
            ax = fmaf(pw, vn.x - vold.x, ax);
            ay = fmaf(pw, vn.y - vold.y, ay);
        }
        float2 o;
        o.x = __uint_as_float(f2tf32(ax));
        o.y = __uint_as_float(f2tf32(ay));
        *(float2*)(g_att + (size_t)b * DWM + d) = o;
    }
}

// ---------------- launcher ---------------------------------------------------
extern "C" void kernel_launch(void* const* d_in, const int* in_sizes, int n_in,
                              void* d_out, int out_size)
{
    const float* x     = (const float*)d_in[0];
    const void*  reset = d_in[1];
    const float* wmK   = (const float*)d_in[2];
    const float* wmV   = (const float*)d_in[3];
    const void*  valid = d_in[4];
    const int*   ptr   = (const int*)d_in[5];
    const float* Wq    = (const float*)d_in[6];
    const float* bq    = (const float*)d_in[7];
    const float* Wk    = (const float*)d_in[8];
    const float* bk    = (const float*)d_in[9];
    const float* Wv    = (const float*)d_in[10];
    const float* bv    = (const float*)d_in[11];
    const float* Wo    = (const float*)d_in[12];
    const float* bo    = (const float*)d_in[13];
    float*       y     = (float*)d_out;

    cudaFuncSetAttribute(qkv_gemm_tc, cudaFuncAttributeMaxDynamicSharedMemorySize, TCSM_BYTES);
    cudaFuncSetAttribute(out_gemm_tc, cudaFuncAttributeMaxDynamicSharedMemorySize, TCSM_BYTES);

    // fused: tf32 pre-round (blocks 0..2047) + row compaction (block 2048)
    convert_kernel<<<2049, 256>>>(x, Wq, Wk, Wv, Wo, reset, valid);

    dim3 gQKV(BSZ / BM, 12);            // 16 x 12; Q/K tail tiles self-disable
    qkv_gemm_tc<<<gQKV, 256, TCSM_BYTES>>>(bq, bk, bv);

    attn_kernel<<<BSZ, 256>>>(wmK, wmV, valid, ptr);

    dim3 gOut(BSZ / BM, DIM / BN);      // 16 x 8 = 128 CTAs
    out_gemm_tc<<<gOut, 256, TCSM_BYTES>>>(bo, y);
}